// round 6
// baseline (speedup 1.0000x reference)
#include <cuda_runtime.h>

// Problem constants
#define BS   64
#define SEQ  512
#define H    768
#define TT   64   // topic count per batch
#define KK   64   // token count per batch

// Per-batch factored weight vectors:
// A[b][m][p], m in {cls_c0, cls_c1, topic_c0, topic_c1, token_c0, token_c1}, p in [0,768)
// A[b][2w+c][g*8+j] = sum_i d0[b][g*8+i] * W_w[c][g*64 + i*8 + j]
__device__ float g_A[BS * 6 * H];

// ---------------------------------------------------------------------------
// Kernel 1: build d0 (domain embedding) and the 6 factored A vectors per batch
// ---------------------------------------------------------------------------
__global__ void __launch_bounds__(256) build_A_kernel(
    const float* __restrict__ Wsrc,   // [862, 384]
    const float* __restrict__ Wtgt,   // [862, 384]
    const float* __restrict__ Wcls,   // [2, 6144]
    const float* __restrict__ Wtopic, // [2, 6144]
    const float* __restrict__ Wtoken, // [2, 6144]
    const int*   __restrict__ src_ids,
    const int*   __restrict__ tgt_ids)
{
    const int b   = blockIdx.x;
    const int tid = threadIdx.x;

    __shared__ float d0[H];  // concat(src_emb, tgt_emb)

    const float* __restrict__ s = Wsrc + (size_t)src_ids[b] * 384;
    const float* __restrict__ t = Wtgt + (size_t)tgt_ids[b] * 384;
    for (int i = tid; i < 384; i += blockDim.x) {
        d0[i]       = s[i];
        d0[384 + i] = t[i];
    }
    __syncthreads();

    const float* Ws[3] = {Wcls, Wtopic, Wtoken};
    float* __restrict__ Ab = g_A + (size_t)b * 6 * H;

    for (int e = tid; e < 6 * H; e += blockDim.x) {
        const int m = e / H;          // 0..5
        const int p = e - m * H;      // 0..767
        const int w = m >> 1;
        const int c = m & 1;
        const int g = p >> 3;
        const int j = p & 7;
        const float* __restrict__ W = Ws[w] + c * 6144 + g * 64 + j;
        const float* __restrict__ d = d0 + g * 8;
        float acc = 0.f;
#pragma unroll
        for (int i = 0; i < 8; i++)
            acc = fmaf(d[i], W[i * 8], acc);
        Ab[e] = acc;
    }
}

// ---------------------------------------------------------------------------
// Kernel 2: 129 rows per batch (1 cls + 64 topic + 64 token).
// Warp-per-row: gather hidden row (768 f32 via float4), dot vs 2 A vectors
// from smem, shfl-reduce, mask*dot+bias, optional 2-way softmax, store.
// ---------------------------------------------------------------------------
__global__ void __launch_bounds__(256) rows_kernel(
    const float* __restrict__ hidden,     // [BS, SEQ, H]
    const float* __restrict__ b_cls,      // [2]
    const float* __restrict__ b_topic,    // [2]
    const float* __restrict__ b_token,    // [2]
    const int*   __restrict__ topic_inds, // [BS, TT]
    const float* __restrict__ topic_mask, // [BS, TT]
    const int*   __restrict__ token_inds, // [BS, KK]
    const float* __restrict__ token_mask, // [BS, KK]
    float* __restrict__ out)              // [128 | 8192 | 8192]
{
    const int b   = blockIdx.x;
    const int tid = threadIdx.x;

    __shared__ float sA[6 * H];  // 18 KB

    {
        const float* __restrict__ Ab = g_A + (size_t)b * 6 * H;
        for (int e = tid; e < 6 * H; e += blockDim.x)
            sA[e] = Ab[e];
    }
    __syncthreads();

    const int warp  = tid >> 5;
    const int lane  = tid & 31;
    const int wpb   = blockDim.x >> 5;          // warps per block (8)
    const int nwpb  = gridDim.y * wpb;          // warps per batch (64)
    const int w0    = blockIdx.y * wpb + warp;  // this warp's start row

    const float* __restrict__ hb = hidden + (size_t)b * SEQ * H;

    for (int r = w0; r < 1 + TT + KK; r += nwpb) {
        const float* hrow;
        float  mask = 1.f, bias0, bias1;
        float* outp;
        int    m0;
        bool   do_softmax;

        if (r == 0) {
            m0 = 0;
            hrow = hb;                       // hidden[b, 0, :]
            bias0 = b_cls[0]; bias1 = b_cls[1];
            outp = out + b * 2;
            do_softmax = true;
        } else if (r < 1 + TT) {
            const int l = r - 1;
            const int idx = topic_inds[b * TT + l];
            mask = topic_mask[b * TT + l];
            m0 = 2;
            hrow = hb + (size_t)idx * H;
            bias0 = b_topic[0]; bias1 = b_topic[1];
            outp = out + 128 + (b * TT + l) * 2;
            do_softmax = true;
        } else {
            const int l = r - (1 + TT);
            const int idx = token_inds[b * KK + l];
            mask = token_mask[b * KK + l];
            m0 = 4;
            hrow = hb + (size_t)idx * H;
            bias0 = b_token[0]; bias1 = b_token[1];
            outp = out + 128 + BS * TT * 2 + (b * KK + l) * 2;
            do_softmax = false;
        }

        const float4* __restrict__ h4 = (const float4*)hrow;
        const float4* __restrict__ a0 = (const float4*)(sA + m0 * H);
        const float4* __restrict__ a1 = (const float4*)(sA + (m0 + 1) * H);

        float acc0 = 0.f, acc1 = 0.f;
#pragma unroll
        for (int k = 0; k < 6; k++) {         // 192 float4s / 32 lanes
            const int p = lane + k * 32;
            const float4 h = h4[p];
            const float4 x = a0[p];
            const float4 y = a1[p];
            acc0 = fmaf(h.x, x.x, fmaf(h.y, x.y, fmaf(h.z, x.z, fmaf(h.w, x.w, acc0))));
            acc1 = fmaf(h.x, y.x, fmaf(h.y, y.y, fmaf(h.z, y.z, fmaf(h.w, y.w, acc1))));
        }
#pragma unroll
        for (int o = 16; o; o >>= 1) {
            acc0 += __shfl_xor_sync(0xFFFFFFFFu, acc0, o);
            acc1 += __shfl_xor_sync(0xFFFFFFFFu, acc1, o);
        }

        if (lane == 0) {
            const float x0 = fmaf(mask, acc0, bias0);
            const float x1 = fmaf(mask, acc1, bias1);
            if (do_softmax) {
                const float mx = fmaxf(x0, x1);
                const float e0 = __expf(x0 - mx);
                const float e1 = __expf(x1 - mx);
                const float inv = 1.f / (e0 + e1);
                outp[0] = e0 * inv;
                outp[1] = e1 * inv;
            } else {
                outp[0] = x0;
                outp[1] = x1;
            }
        }
    }
}

// ---------------------------------------------------------------------------
// Launch
// ---------------------------------------------------------------------------
extern "C" void kernel_launch(void* const* d_in, const int* in_sizes, int n_in,
                              void* d_out, int out_size)
{
    const float* hidden     = (const float*)d_in[0];   // [64,512,768]
    const float* Wsrc       = (const float*)d_in[1];   // [862,384]
    const float* Wtgt       = (const float*)d_in[2];   // [862,384]
    const float* W_cls      = (const float*)d_in[3];   // [2,6144]
    const float* b_cls      = (const float*)d_in[4];   // [2]
    const float* W_topic    = (const float*)d_in[5];   // [2,6144]
    const float* b_topic    = (const float*)d_in[6];   // [2]
    const float* W_token    = (const float*)d_in[7];   // [2,6144]
    const float* b_token    = (const float*)d_in[8];   // [2]
    const int*   source_ids = (const int*)d_in[9];     // [64]
    const int*   target_ids = (const int*)d_in[10];    // [64]
    // d_in[11] ent_inds, d_in[12] ent_mask: unused by reference outputs
    const int*   topic_inds = (const int*)d_in[13];    // [64,64]
    const float* topic_mask = (const float*)d_in[14];  // [64,64]
    const int*   token_inds = (const int*)d_in[15];    // [64,64]
    const float* token_mask = (const float*)d_in[16];  // [64,64]

    float* out = (float*)d_out;

    build_A_kernel<<<BS, 256>>>(Wsrc, Wtgt, W_cls, W_topic, W_token,
                                source_ids, target_ids);

    dim3 grid(BS, 8);
    rows_kernel<<<grid, 256>>>(hidden, b_cls, b_topic, b_token,
                               topic_inds, topic_mask,
                               token_inds, token_mask, out);
}

// round 7
// speedup vs baseline: 1.3809x; 1.3809x over previous
#include <cuda_runtime.h>

// Problem constants
#define BS   64
#define SEQ  512
#define H    768
#define TT   64   // topic count per batch
#define KK   64   // token count per batch

// Per-batch factored weight vectors, 16B-aligned for float4 traffic:
// A[b][m][p], m in {cls_c0, cls_c1, topic_c0, topic_c1, token_c0, token_c1}
__device__ float4 g_A4[BS * 6 * H / 4];

// ---------------------------------------------------------------------------
// Kernel 1: build the 6 factored A vectors per batch.
// grid (BS, 6): block (b, m) computes A[b][m][0..767].
// ---------------------------------------------------------------------------
__global__ void __launch_bounds__(128) build_A_kernel(
    const float* __restrict__ Wsrc,   // [862, 384]
    const float* __restrict__ Wtgt,   // [862, 384]
    const float* __restrict__ Wcls,   // [2, 6144]
    const float* __restrict__ Wtopic, // [2, 6144]
    const float* __restrict__ Wtoken, // [2, 6144]
    const int*   __restrict__ src_ids,
    const int*   __restrict__ tgt_ids)
{
    const int b   = blockIdx.x;
    const int m   = blockIdx.y;      // 0..5
    const int tid = threadIdx.x;

    __shared__ float d0[H];  // concat(src_emb, tgt_emb)

    const float* __restrict__ s = Wsrc + (size_t)src_ids[b] * 384;
    const float* __restrict__ t = Wtgt + (size_t)tgt_ids[b] * 384;
    for (int i = tid; i < 384; i += blockDim.x) {
        d0[i]       = s[i];
        d0[384 + i] = t[i];
    }
    __syncthreads();

    const int w = m >> 1;
    const int c = m & 1;
    const float* __restrict__ Wbase =
        (w == 0 ? Wcls : (w == 1 ? Wtopic : Wtoken)) + c * 6144;

    float* __restrict__ Ab = ((float*)g_A4) + ((size_t)b * 6 + m) * H;

#pragma unroll
    for (int e = tid; e < H; e += 128) {
        const int g = e >> 3;
        const int j = e & 7;
        const float* __restrict__ W = Wbase + g * 64 + j;
        const float* __restrict__ d = d0 + g * 8;
        float acc = 0.f;
#pragma unroll
        for (int i = 0; i < 8; i++)
            acc = fmaf(d[i], W[i * 8], acc);
        Ab[e] = acc;
    }

    // Allow the dependent rows_kernel grid to launch (its DRAM gather
    // prologue is independent of g_A).
#if __CUDA_ARCH__ >= 900
    cudaTriggerProgrammaticLaunchCompletion();
#endif
}

// ---------------------------------------------------------------------------
// Kernel 2: 129 rows per batch (1 cls + 64 topic + 64 token), ONE row per warp.
// Phase 1 (pre-dependency): gather the full 3KB hidden row into registers —
//   6 independent LDG.128 per lane, all in flight at once.
// Phase 2 (post cudaGridDependencySynchronize): stage A into smem, dot, reduce.
// grid (BS, 9) x 512 threads -> 144 warps per batch, 129 active.
// ---------------------------------------------------------------------------
__global__ void __launch_bounds__(512) rows_kernel(
    const float* __restrict__ hidden,     // [BS, SEQ, H]
    const float* __restrict__ b_cls,      // [2]
    const float* __restrict__ b_topic,    // [2]
    const float* __restrict__ b_token,    // [2]
    const int*   __restrict__ topic_inds, // [BS, TT]
    const float* __restrict__ topic_mask, // [BS, TT]
    const int*   __restrict__ token_inds, // [BS, KK]
    const float* __restrict__ token_mask, // [BS, KK]
    float* __restrict__ out)              // [128 | 8192 | 8192]
{
    const int b    = blockIdx.x;
    const int tid  = threadIdx.x;
    const int warp = tid >> 5;
    const int lane = tid & 31;
    const int r    = blockIdx.y * 16 + warp;   // row id, 0..143

    const bool active = (r < 1 + TT + KK);

    // ---------- Phase 1: independent prologue (no g_A dependence) ----------
    float  mask = 1.f, bias0 = 0.f, bias1 = 0.f;
    float* outp = out;
    int    m0 = 0;
    bool   do_softmax = true;
    float4 h0, h1, h2, h3, h4v, h5;

    if (active) {
        const float* __restrict__ hb = hidden + (size_t)b * SEQ * H;
        const float* hrow;

        if (r == 0) {
            m0 = 0;
            hrow = hb;                        // hidden[b, 0, :]
            bias0 = b_cls[0]; bias1 = b_cls[1];
            outp = out + b * 2;
            do_softmax = true;
        } else if (r < 1 + TT) {
            const int l = r - 1;
            const int idx = topic_inds[b * TT + l];
            mask = topic_mask[b * TT + l];
            m0 = 2;
            hrow = hb + (size_t)idx * H;
            bias0 = b_topic[0]; bias1 = b_topic[1];
            outp = out + 128 + (b * TT + l) * 2;
            do_softmax = true;
        } else {
            const int l = r - (1 + TT);
            const int idx = token_inds[b * KK + l];
            mask = token_mask[b * KK + l];
            m0 = 4;
            hrow = hb + (size_t)idx * H;
            bias0 = b_token[0]; bias1 = b_token[1];
            outp = out + 128 + BS * TT * 2 + (b * KK + l) * 2;
            do_softmax = false;
        }

        // Batch all 6 global loads of this row into registers (max MLP).
        const float4* __restrict__ h4 = (const float4*)hrow;
        h0  = h4[lane];
        h1  = h4[lane + 32];
        h2  = h4[lane + 64];
        h3  = h4[lane + 96];
        h4v = h4[lane + 128];
        h5  = h4[lane + 160];
    }

    // ---------- Dependency point: g_A must now be valid ----------
#if __CUDA_ARCH__ >= 900
    cudaGridDependencySynchronize();
#endif

    __shared__ float4 sA4[6 * H / 4];  // 18 KB
    {
        const float4* __restrict__ Ab = g_A4 + (size_t)b * (6 * H / 4);
#pragma unroll
        for (int e = tid; e < 6 * H / 4; e += 512)
            sA4[e] = Ab[e];
    }
    __syncthreads();

    if (active) {
        const float4* __restrict__ a0 = sA4 + m0 * (H / 4);
        const float4* __restrict__ a1 = a0 + (H / 4);

        float acc0 = 0.f, acc1 = 0.f;
        {
            float4 h, x, y;
#define DOT_STEP(HV, OFF)                                                        \
            h = (HV); x = a0[lane + (OFF)]; y = a1[lane + (OFF)];                \
            acc0 = fmaf(h.x, x.x, fmaf(h.y, x.y, fmaf(h.z, x.z, fmaf(h.w, x.w, acc0)))); \
            acc1 = fmaf(h.x, y.x, fmaf(h.y, y.y, fmaf(h.z, y.z, fmaf(h.w, y.w, acc1))));
            DOT_STEP(h0,   0)
            DOT_STEP(h1,  32)
            DOT_STEP(h2,  64)
            DOT_STEP(h3,  96)
            DOT_STEP(h4v, 128)
            DOT_STEP(h5, 160)
#undef DOT_STEP
        }

#pragma unroll
        for (int o = 16; o; o >>= 1) {
            acc0 += __shfl_xor_sync(0xFFFFFFFFu, acc0, o);
            acc1 += __shfl_xor_sync(0xFFFFFFFFu, acc1, o);
        }

        if (lane == 0) {
            const float x0 = fmaf(mask, acc0, bias0);
            const float x1 = fmaf(mask, acc1, bias1);
            if (do_softmax) {
                const float mx = fmaxf(x0, x1);
                const float e0 = __expf(x0 - mx);
                const float e1 = __expf(x1 - mx);
                const float inv = 1.f / (e0 + e1);
                outp[0] = e0 * inv;
                outp[1] = e1 * inv;
            } else {
                outp[0] = x0;
                outp[1] = x1;
            }
        }
    }
}

// ---------------------------------------------------------------------------
// Launch: build_A, then rows_kernel with programmatic dependent launch so its
// DRAM gather prologue overlaps build_A's tail.
// ---------------------------------------------------------------------------
extern "C" void kernel_launch(void* const* d_in, const int* in_sizes, int n_in,
                              void* d_out, int out_size)
{
    const float* hidden     = (const float*)d_in[0];   // [64,512,768]
    const float* Wsrc       = (const float*)d_in[1];   // [862,384]
    const float* Wtgt       = (const float*)d_in[2];   // [862,384]
    const float* W_cls      = (const float*)d_in[3];   // [2,6144]
    const float* b_cls      = (const float*)d_in[4];   // [2]
    const float* W_topic    = (const float*)d_in[5];   // [2,6144]
    const float* b_topic    = (const float*)d_in[6];   // [2]
    const float* W_token    = (const float*)d_in[7];   // [2,6144]
    const float* b_token    = (const float*)d_in[8];   // [2]
    const int*   source_ids = (const int*)d_in[9];     // [64]
    const int*   target_ids = (const int*)d_in[10];    // [64]
    // d_in[11] ent_inds, d_in[12] ent_mask: unused by reference outputs
    const int*   topic_inds = (const int*)d_in[13];    // [64,64]
    const float* topic_mask = (const float*)d_in[14];  // [64,64]
    const int*   token_inds = (const int*)d_in[15];    // [64,64]
    const float* token_mask = (const float*)d_in[16];  // [64,64]

    float* out = (float*)d_out;

    build_A_kernel<<<dim3(BS, 6), 128>>>(Wsrc, Wtgt, W_cls, W_topic, W_token,
                                         source_ids, target_ids);

    cudaLaunchConfig_t cfg = {};
    cfg.gridDim          = dim3(BS, 9);
    cfg.blockDim         = dim3(512);
    cfg.dynamicSmemBytes = 0;
    cfg.stream           = 0;
    cudaLaunchAttribute attr[1];
    attr[0].id = cudaLaunchAttributeProgrammaticStreamSerialization;
    attr[0].val.programmaticStreamSerializationAllowed = 1;
    cfg.attrs    = attr;
    cfg.numAttrs = 1;

    cudaLaunchKernelEx(&cfg, rows_kernel, hidden, b_cls, b_topic, b_token,
                       topic_inds, topic_mask, token_inds, token_mask, out);
}

// round 8
// speedup vs baseline: 1.4017x; 1.0151x over previous
#include <cuda_runtime.h>

// Problem constants
#define BS   64
#define SEQ  512
#define H    768
#define TT   64   // topic count per batch
#define KK   64   // token count per batch

#define ROWS_PER_BLOCK 8      // warps per block = rows per block
#define THREADS        256
#define GRID_Y         17     // 17*8 = 136 >= 129 rows

// Per-batch factored weight vectors, float4 layout:
// A[b][m][p], m in {cls_c0, cls_c1, topic_c0, topic_c1, token_c0, token_c1}
__device__ float4 g_A4[BS * 6 * H / 4];

// ---------------------------------------------------------------------------
// Kernel 1: build the 6 factored A vectors per batch.
// grid (BS, 6): block (b, m) computes A[b][m][0..767].
// ---------------------------------------------------------------------------
__global__ void __launch_bounds__(128) build_A_kernel(
    const float* __restrict__ Wsrc,   // [862, 384]
    const float* __restrict__ Wtgt,   // [862, 384]
    const float* __restrict__ Wcls,   // [2, 6144]
    const float* __restrict__ Wtopic, // [2, 6144]
    const float* __restrict__ Wtoken, // [2, 6144]
    const int*   __restrict__ src_ids,
    const int*   __restrict__ tgt_ids)
{
    const int b   = blockIdx.x;
    const int m   = blockIdx.y;      // 0..5
    const int tid = threadIdx.x;

    __shared__ float d0[H];  // concat(src_emb, tgt_emb)

    const float* __restrict__ s = Wsrc + (size_t)src_ids[b] * 384;
    const float* __restrict__ t = Wtgt + (size_t)tgt_ids[b] * 384;
    for (int i = tid; i < 384; i += blockDim.x) {
        d0[i]       = s[i];
        d0[384 + i] = t[i];
    }
    __syncthreads();

    const int w = m >> 1;
    const int c = m & 1;
    const float* __restrict__ Wbase =
        (w == 0 ? Wcls : (w == 1 ? Wtopic : Wtoken)) + c * 6144;

    float* __restrict__ Ab = ((float*)g_A4) + ((size_t)b * 6 + m) * H;

#pragma unroll
    for (int e = tid; e < H; e += 128) {
        const int g = e >> 3;
        const int j = e & 7;
        const float* __restrict__ W = Wbase + g * 64 + j;
        const float* __restrict__ d = d0 + g * 8;
        float acc = 0.f;
#pragma unroll
        for (int i = 0; i < 8; i++)
            acc = fmaf(d[i], W[i * 8], acc);
        Ab[e] = acc;
    }

#if __CUDA_ARCH__ >= 900
    cudaTriggerProgrammaticLaunchCompletion();
#endif
}

// ---------------------------------------------------------------------------
// Kernel 2: one row per warp, cp.async-staged.
//   Phase 1 (pre-dependency): issue LDGSTS for the full 3KB hidden row into
//     smem — zero register cost, all rows' traffic in flight at once.
//   Phase 2 (post cudaGridDependencySynchronize): LDGSTS the A vectors,
//     commit+wait once, smem-vs-smem dot, shfl reduce, epilogue.
// grid (BS, 17) x 256 threads.
// ---------------------------------------------------------------------------
__global__ void __launch_bounds__(THREADS) rows_kernel(
    const float* __restrict__ hidden,     // [BS, SEQ, H]
    const float* __restrict__ b_cls,      // [2]
    const float* __restrict__ b_topic,    // [2]
    const float* __restrict__ b_token,    // [2]
    const int*   __restrict__ topic_inds, // [BS, TT]
    const float* __restrict__ topic_mask, // [BS, TT]
    const int*   __restrict__ token_inds, // [BS, KK]
    const float* __restrict__ token_mask, // [BS, KK]
    float* __restrict__ out)              // [128 | 8192 | 8192]
{
    const int b    = blockIdx.x;
    const int tid  = threadIdx.x;
    const int warp = tid >> 5;
    const int lane = tid & 31;
    const int r    = blockIdx.y * ROWS_PER_BLOCK + warp;   // 0..135

    const bool active = (r < 1 + TT + KK);

    __shared__ float4 sH[ROWS_PER_BLOCK * (H / 4)];  // 24 KB row stage
    __shared__ float4 sA[6 * (H / 4)];               // 18 KB A vectors

    // ---------- Phase 1: independent prologue (no g_A dependence) ----------
    float  mask = 1.f, bias0 = 0.f, bias1 = 0.f;
    float* outp = out;
    int    m0 = 0;
    bool   do_softmax = true;

    if (active) {
        const float* __restrict__ hb = hidden + (size_t)b * SEQ * H;
        const float* hrow;

        if (r == 0) {
            m0 = 0;
            hrow = hb;                        // hidden[b, 0, :]
            bias0 = b_cls[0]; bias1 = b_cls[1];
            outp = out + b * 2;
            do_softmax = true;
        } else if (r < 1 + TT) {
            const int l = r - 1;
            const int idx = topic_inds[b * TT + l];
            mask = topic_mask[b * TT + l];
            m0 = 2;
            hrow = hb + (size_t)idx * H;
            bias0 = b_topic[0]; bias1 = b_topic[1];
            outp = out + 128 + (b * TT + l) * 2;
            do_softmax = true;
        } else {
            const int l = r - (1 + TT);
            const int idx = token_inds[b * KK + l];
            mask = token_mask[b * KK + l];
            m0 = 4;
            hrow = hb + (size_t)idx * H;
            bias0 = b_token[0]; bias1 = b_token[1];
            outp = out + 128 + BS * TT * 2 + (b * KK + l) * 2;
            do_softmax = false;
        }

        // Stage the full row into smem via cp.async: 6 x 16B per lane,
        // no register footprint, all in flight immediately.
        const float4* __restrict__ src = (const float4*)hrow;
        unsigned dst = (unsigned)__cvta_generic_to_shared(
            &sH[warp * (H / 4) + lane]);
#pragma unroll
        for (int k = 0; k < 6; k++) {
            asm volatile("cp.async.cg.shared.global [%0], [%1], 16;\n"
                         :: "r"(dst + (unsigned)(k * 32 * 16)),
                            "l"(src + lane + k * 32));
        }
    }

    // ---------- Dependency point: g_A must now be valid ----------
#if __CUDA_ARCH__ >= 900
    cudaGridDependencySynchronize();
#endif

    // Stage A vectors (also cp.async; joins the same commit group).
    {
        const float4* __restrict__ Ab = g_A4 + (size_t)b * (6 * H / 4);
        for (int e = tid; e < 6 * H / 4; e += THREADS) {
            unsigned d = (unsigned)__cvta_generic_to_shared(&sA[e]);
            asm volatile("cp.async.cg.shared.global [%0], [%1], 16;\n"
                         :: "r"(d), "l"(Ab + e));
        }
    }
    asm volatile("cp.async.commit_group;\n");
    asm volatile("cp.async.wait_group 0;\n");
    __syncthreads();

    if (active) {
        const float4* __restrict__ h4 = sH + warp * (H / 4);
        const float4* __restrict__ a0 = sA + m0 * (H / 4);
        const float4* __restrict__ a1 = a0 + (H / 4);

        float acc0 = 0.f, acc1 = 0.f;
#pragma unroll
        for (int k = 0; k < 6; k++) {
            const int p = lane + k * 32;
            const float4 h = h4[p];
            const float4 x = a0[p];
            const float4 y = a1[p];
            acc0 = fmaf(h.x, x.x, fmaf(h.y, x.y, fmaf(h.z, x.z, fmaf(h.w, x.w, acc0))));
            acc1 = fmaf(h.x, y.x, fmaf(h.y, y.y, fmaf(h.z, y.z, fmaf(h.w, y.w, acc1))));
        }

#pragma unroll
        for (int o = 16; o; o >>= 1) {
            acc0 += __shfl_xor_sync(0xFFFFFFFFu, acc0, o);
            acc1 += __shfl_xor_sync(0xFFFFFFFFu, acc1, o);
        }

        if (lane == 0) {
            const float x0 = fmaf(mask, acc0, bias0);
            const float x1 = fmaf(mask, acc1, bias1);
            if (do_softmax) {
                const float mx = fmaxf(x0, x1);
                const float e0 = __expf(x0 - mx);
                const float e1 = __expf(x1 - mx);
                const float inv = 1.f / (e0 + e1);
                outp[0] = e0 * inv;
                outp[1] = e1 * inv;
            } else {
                outp[0] = x0;
                outp[1] = x1;
            }
        }
    }
}

// ---------------------------------------------------------------------------
// Launch: build_A, then rows_kernel with programmatic dependent launch so its
// cp.async gather prologue overlaps build_A's tail.
// ---------------------------------------------------------------------------
extern "C" void kernel_launch(void* const* d_in, const int* in_sizes, int n_in,
                              void* d_out, int out_size)
{
    const float* hidden     = (const float*)d_in[0];   // [64,512,768]
    const float* Wsrc       = (const float*)d_in[1];   // [862,384]
    const float* Wtgt       = (const float*)d_in[2];   // [862,384]
    const float* W_cls      = (const float*)d_in[3];   // [2,6144]
    const float* b_cls      = (const float*)d_in[4];   // [2]
    const float* W_topic    = (const float*)d_in[5];   // [2,6144]
    const float* b_topic    = (const float*)d_in[6];   // [2]
    const float* W_token    = (const float*)d_in[7];   // [2,6144]
    const float* b_token    = (const float*)d_in[8];   // [2]
    const int*   source_ids = (const int*)d_in[9];     // [64]
    const int*   target_ids = (const int*)d_in[10];    // [64]
    // d_in[11] ent_inds, d_in[12] ent_mask: unused by reference outputs
    const int*   topic_inds = (const int*)d_in[13];    // [64,64]
    const float* topic_mask = (const float*)d_in[14];  // [64,64]
    const int*   token_inds = (const int*)d_in[15];    // [64,64]
    const float* token_mask = (const float*)d_in[16];  // [64,64]

    float* out = (float*)d_out;

    build_A_kernel<<<dim3(BS, 6), 128>>>(Wsrc, Wtgt, W_cls, W_topic, W_token,
                                         source_ids, target_ids);

    cudaLaunchConfig_t cfg = {};
    cfg.gridDim          = dim3(BS, GRID_Y);
    cfg.blockDim         = dim3(THREADS);
    cfg.dynamicSmemBytes = 0;
    cfg.stream           = 0;
    cudaLaunchAttribute attr[1];
    attr[0].id = cudaLaunchAttributeProgrammaticStreamSerialization;
    attr[0].val.programmaticStreamSerializationAllowed = 1;
    cfg.attrs    = attr;
    cfg.numAttrs = 1;

    cudaLaunchKernelEx(&cfg, rows_kernel, hidden, b_cls, b_topic, b_token,
                       topic_inds, topic_mask, token_inds, token_mask, out);
}